// round 1
// baseline (speedup 1.0000x reference)
#include <cuda_runtime.h>
#include <cuda_bf16.h>

#define Bsz 64
#define T   256
#define Isz 2048
#define Hsz 4096
#define Osz 1024

#define THRESHOLD 1.0f
#define DECAY     0.9f

// Scratch (device globals — no allocation allowed)
__device__ float g_xbar[T * Isz];   // 2 MB
__device__ float g_cur [T * Hsz];   // 4 MB
__device__ float g_agg [Hsz];       // 16 KB

// ---------------------------------------------------------------------------
// 1) Batch reduction: xbar[t,i] = (1/B) * sum_b x[b,t,i]
//    x: [B, T, I] row-major. Vectorized float4, one output float4 per thread.
// ---------------------------------------------------------------------------
__global__ void reduce_batch_kernel(const float* __restrict__ x) {
    const int idx = blockIdx.x * blockDim.x + threadIdx.x;  // over T*I/4
    const int n4  = (T * Isz) / 4;
    if (idx >= n4) return;
    const float4* __restrict__ x4 = reinterpret_cast<const float4*>(x);
    float ax = 0.f, ay = 0.f, az = 0.f, aw = 0.f;
#pragma unroll 8
    for (int b = 0; b < Bsz; ++b) {
        float4 v = x4[(size_t)b * n4 + idx];
        ax += v.x; ay += v.y; az += v.z; aw += v.w;
    }
    const float s = 1.0f / (float)Bsz;
    float4 r;
    r.x = ax * s; r.y = ay * s; r.z = az * s; r.w = aw * s;
    reinterpret_cast<float4*>(g_xbar)[idx] = r;
}

// ---------------------------------------------------------------------------
// 2) FP32 tiled GEMM: cur[T,H] = xbar[T,I] @ W_in[I,H] + b_in
//    64x64 tile, BK=16, 256 threads, 4x4 per-thread microtile, float4 LDS.
// ---------------------------------------------------------------------------
#define BM 64
#define BN 64
#define BK 16

__global__ __launch_bounds__(256) void gemm_in_kernel(
    const float* __restrict__ W_in, const float* __restrict__ b_in)
{
    __shared__ float As[BK][BM];  // transposed A tile
    __shared__ float Bs[BK][BN];

    const int tid = threadIdx.x;       // 0..255
    const int tx  = tid & 15;          // n micro-index
    const int ty  = tid >> 4;          // m micro-index
    const int n0  = blockIdx.x * BN;
    const int m0  = blockIdx.y * BM;

    // A-load mapping: 64 rows x 4 float4 per row
    const int a_row = tid >> 2;        // 0..63
    const int a_c4  = tid & 3;         // 0..3  (float4 column within BK)
    // B-load mapping: 16 rows x 16 float4 per row
    const int b_row = tid >> 4;        // 0..15
    const int b_c4  = tid & 15;        // 0..15

    float acc[4][4];
#pragma unroll
    for (int i = 0; i < 4; ++i)
#pragma unroll
        for (int j = 0; j < 4; ++j) acc[i][j] = 0.f;

    for (int k0 = 0; k0 < Isz; k0 += BK) {
        // Load A tile (xbar) -> As transposed
        {
            const float4 v = *reinterpret_cast<const float4*>(
                &g_xbar[(size_t)(m0 + a_row) * Isz + k0 + a_c4 * 4]);
            As[a_c4 * 4 + 0][a_row] = v.x;
            As[a_c4 * 4 + 1][a_row] = v.y;
            As[a_c4 * 4 + 2][a_row] = v.z;
            As[a_c4 * 4 + 3][a_row] = v.w;
        }
        // Load B tile (W_in) directly
        {
            const float4 v = *reinterpret_cast<const float4*>(
                &W_in[(size_t)(k0 + b_row) * Hsz + n0 + b_c4 * 4]);
            *reinterpret_cast<float4*>(&Bs[b_row][b_c4 * 4]) = v;
        }
        __syncthreads();

#pragma unroll
        for (int k = 0; k < BK; ++k) {
            const float4 a = *reinterpret_cast<const float4*>(&As[k][ty * 4]);
            const float4 b = *reinterpret_cast<const float4*>(&Bs[k][tx * 4]);
            const float av[4] = {a.x, a.y, a.z, a.w};
            const float bv[4] = {b.x, b.y, b.z, b.w};
#pragma unroll
            for (int i = 0; i < 4; ++i)
#pragma unroll
                for (int j = 0; j < 4; ++j)
                    acc[i][j] += av[i] * bv[j];
        }
        __syncthreads();
    }

    // Epilogue: add bias, store
    const int nbase = n0 + tx * 4;
    const float4 bia = *reinterpret_cast<const float4*>(&b_in[nbase]);
    const float bv[4] = {bia.x, bia.y, bia.z, bia.w};
#pragma unroll
    for (int i = 0; i < 4; ++i) {
        float4 r;
        r.x = acc[i][0] + bv[0];
        r.y = acc[i][1] + bv[1];
        r.z = acc[i][2] + bv[2];
        r.w = acc[i][3] + bv[3];
        *reinterpret_cast<float4*>(
            &g_cur[(size_t)(m0 + ty * 4 + i) * Hsz + nbase]) = r;
    }
}

// ---------------------------------------------------------------------------
// 3) LIF scan over T, per neuron h. agg[h] = mean_t spike[t,h]
// ---------------------------------------------------------------------------
__global__ void scan_kernel(const float* __restrict__ m0) {
    const int h = blockIdx.x * blockDim.x + threadIdx.x;
    if (h >= Hsz) return;
    float m = m0[h];
    float s = 0.f;
#pragma unroll 4
    for (int t = 0; t < T; ++t) {
        m = DECAY * m + g_cur[(size_t)t * Hsz + h];
        if (m > THRESHOLD) { s += 1.0f; m = 0.0f; }
    }
    g_agg[h] = s * (1.0f / (float)T);
}

// ---------------------------------------------------------------------------
// 4) Output GEMV: out[O] = agg[H] @ W_out[H,O] + b_out
//    Split over H for parallelism; atomicAdd partials.
// ---------------------------------------------------------------------------
__global__ void out_init_kernel(float* __restrict__ out,
                                const float* __restrict__ b_out) {
    const int o = blockIdx.x * blockDim.x + threadIdx.x;
    if (o < Osz) out[o] = b_out[o];
}

#define OUT_OB 128   // o's per block
#define OUT_HB 256   // h's per block

__global__ __launch_bounds__(OUT_OB) void out_gemv_kernel(
    const float* __restrict__ W_out, float* __restrict__ out)
{
    __shared__ float s_agg[OUT_HB];
    const int obase = blockIdx.x * OUT_OB;
    const int hbase = blockIdx.y * OUT_HB;
    const int tid   = threadIdx.x;

    for (int i = tid; i < OUT_HB; i += OUT_OB)
        s_agg[i] = g_agg[hbase + i];
    __syncthreads();

    const int o = obase + tid;
    float acc = 0.f;
#pragma unroll 8
    for (int hh = 0; hh < OUT_HB; ++hh)
        acc += s_agg[hh] * W_out[(size_t)(hbase + hh) * Osz + o];
    atomicAdd(&out[o], acc);
}

// ---------------------------------------------------------------------------
extern "C" void kernel_launch(void* const* d_in, const int* in_sizes, int n_in,
                              void* d_out, int out_size) {
    const float* x     = (const float*)d_in[0];  // [B,T,I]
    const float* W_in  = (const float*)d_in[1];  // [I,H]
    const float* b_in  = (const float*)d_in[2];  // [H]
    const float* W_out = (const float*)d_in[3];  // [H,O]
    const float* b_out = (const float*)d_in[4];  // [O]
    const float* m0    = (const float*)d_in[5];  // [H]
    float* out = (float*)d_out;                  // [O]

    // 1) batch reduction: T*I/4 = 131072 threads
    reduce_batch_kernel<<<(T * Isz / 4 + 255) / 256, 256>>>(x);

    // 2) input GEMM: grid (H/64, T/64) = (64, 4)
    dim3 g2(Hsz / BN, T / BM);
    gemm_in_kernel<<<g2, 256>>>(W_in, b_in);

    // 3) scan: H threads
    scan_kernel<<<(Hsz + 255) / 256, 256>>>(m0);

    // 4) output GEMV
    out_init_kernel<<<(Osz + 255) / 256, 256>>>(out, b_out);
    dim3 g4(Osz / OUT_OB, Hsz / OUT_HB);
    out_gemv_kernel<<<g4, OUT_OB>>>(W_out, out);
}

// round 3
// speedup vs baseline: 1.3642x; 1.3642x over previous
#include <cuda_runtime.h>
#include <cuda_bf16.h>
#include <cstdint>

#define Bsz 64
#define T   256
#define Isz 2048
#define Hsz 4096
#define Osz 1024

#define THRESHOLD 1.0f
#define DECAY     0.9f

// ---------------- scratch (device globals; no allocation allowed) ----------
__device__ __nv_bfloat16 g_Ahi[T * Isz];     // 1 MB
__device__ __nv_bfloat16 g_Alo[T * Isz];     // 1 MB
__device__ __nv_bfloat16 g_Bhi[Hsz * Isz];   // 16 MB  [N=4096][K=2048] K-major
__device__ __nv_bfloat16 g_Blo[Hsz * Isz];   // 16 MB
__device__ float g_cur[T * Hsz];             // 4 MB
__device__ float g_agg[Hsz];

// ---------------- PTX helpers ----------------------------------------------
__device__ __forceinline__ uint32_t smem_u32(const void* p) {
    uint32_t a;
    asm("{ .reg .u64 t; cvta.to.shared.u64 t, %1; cvt.u32.u64 %0, t; }"
        : "=r"(a) : "l"(p));
    return a;
}
__device__ __forceinline__ void cp16(uint32_t dst, const void* src) {
    asm volatile("cp.async.cg.shared.global [%0], [%1], 16;" :: "r"(dst), "l"(src));
}
__device__ __forceinline__ void cp_commit() {
    asm volatile("cp.async.commit_group;" ::: "memory");
}
template <int N> __device__ __forceinline__ void cp_wait() {
    asm volatile("cp.async.wait_group %0;" :: "n"(N) : "memory");
}
#define LDSM_X4(r0, r1, r2, r3, addr) \
    asm volatile("ldmatrix.sync.aligned.m8n8.x4.shared.b16 {%0,%1,%2,%3}, [%4];" \
                 : "=r"(r0), "=r"(r1), "=r"(r2), "=r"(r3) : "r"(addr))
#define MMA_BF16(d, a, b0, b1) \
    asm volatile("mma.sync.aligned.m16n8k16.row.col.f32.bf16.bf16.f32 " \
                 "{%0,%1,%2,%3}, {%4,%5,%6,%7}, {%8,%9}, {%0,%1,%2,%3};" \
                 : "+f"((d)[0]), "+f"((d)[1]), "+f"((d)[2]), "+f"((d)[3]) \
                 : "r"((a)[0]), "r"((a)[1]), "r"((a)[2]), "r"((a)[3]), \
                   "r"(b0), "r"(b1))

// ---------------------------------------------------------------------------
// 1) Batch reduce + bf16 hi/lo split: A = mean_b x[b,t,i] -> g_Ahi/g_Alo
// ---------------------------------------------------------------------------
__global__ void reduce_convert_A(const float* __restrict__ x) {
    const int idx = blockIdx.x * blockDim.x + threadIdx.x;  // over T*I/4
    const int n4  = (T * Isz) / 4;
    if (idx >= n4) return;
    const float4* __restrict__ x4 = reinterpret_cast<const float4*>(x);
    float a[4] = {0.f, 0.f, 0.f, 0.f};
#pragma unroll 8
    for (int b = 0; b < Bsz; ++b) {
        float4 v = x4[(size_t)b * n4 + idx];
        a[0] += v.x; a[1] += v.y; a[2] += v.z; a[3] += v.w;
    }
    const float s = 1.0f / (float)Bsz;
    const int base = idx * 4;
#pragma unroll
    for (int i = 0; i < 4; ++i) {
        float v = a[i] * s;
        __nv_bfloat16 hi = __float2bfloat16(v);
        float rem = v - __bfloat162float(hi);
        g_Ahi[base + i] = hi;
        g_Alo[base + i] = __float2bfloat16(rem);
    }
}

// ---------------------------------------------------------------------------
// 2) Transpose + convert W_in [I,H] fp32 -> B_hi/B_lo [H,I] bf16 (K-major)
// ---------------------------------------------------------------------------
__global__ void transpose_convert_B(const float* __restrict__ W) {
    __shared__ float s[32][33];
    const int i0 = blockIdx.y * 32;  // k (row of W)
    const int h0 = blockIdx.x * 32;  // n (col of W)
    const int tx = threadIdx.x;      // 0..31
    const int ty = threadIdx.y;      // 0..7
#pragma unroll
    for (int j = 0; j < 4; ++j) {
        int r = ty + j * 8;
        s[r][tx] = W[(size_t)(i0 + r) * Hsz + h0 + tx];
    }
    __syncthreads();
#pragma unroll
    for (int j = 0; j < 4; ++j) {
        int r = ty + j * 8;          // n offset
        float v = s[tx][r];          // = W[i0+tx][h0+r]
        __nv_bfloat16 hi = __float2bfloat16(v);
        float rem = v - __bfloat162float(hi);
        size_t o = (size_t)(h0 + r) * Isz + i0 + tx;
        g_Bhi[o] = hi;
        g_Blo[o] = __float2bfloat16(rem);
    }
}

// ---------------------------------------------------------------------------
// 3) HMMA bf16 GEMM (3-pass hi/lo): cur[256,4096] = A @ B^T + b_in
//    CTA 64(M)x128(N), 8 warps of 32x32, BK=32, 4-stage cp.async pipeline.
// ---------------------------------------------------------------------------
#define LDA_B 80                     // 40 bf16 padded row stride (bytes)
#define A_TILE_B (64 * LDA_B)        // 5120
#define B_TILE_B (128 * LDA_B)       // 10240
#define STAGE_B  (A_TILE_B + B_TILE_B)
#define NSTAGE 4
#define GEMM_SMEM (NSTAGE * STAGE_B) // 61440
#define NCHUNK 192                   // 3 passes * (2048/32)

__global__ __launch_bounds__(256, 1) void gemm_hmma(const float* __restrict__ b_in) {
    extern __shared__ char smem[];
    const uint32_t sb = smem_u32(smem);
    const int tid  = threadIdx.x;
    const int lane = tid & 31;
    const int wid  = tid >> 5;
    const int m0 = blockIdx.y * 64;
    const int n0 = blockIdx.x * 128;

    const int wm_off = (wid & 1) * 32;   // warp m offset (0/32)
    const int wn_off = (wid >> 1) * 32;  // warp n offset (0/32/64/96)

    float acc[2][4][4];
#pragma unroll
    for (int i = 0; i < 2; ++i)
#pragma unroll
        for (int j = 0; j < 4; ++j)
#pragma unroll
            for (int k = 0; k < 4; ++k) acc[i][j][k] = 0.f;

    auto load_chunk = [&](int c) {
        const int p  = c >> 6;           // pass 0..2
        const int k0 = (c & 63) << 5;    // k offset (32 per chunk)
        const __nv_bfloat16* __restrict__ Asrc = (p == 1) ? g_Alo : g_Ahi;
        const __nv_bfloat16* __restrict__ Bsrc = (p == 2) ? g_Blo : g_Bhi;
        const uint32_t abase = sb + (c & (NSTAGE - 1)) * STAGE_B;
        const uint32_t bbase = abase + A_TILE_B;
        // A: 64 rows x 4 cp16 = 256 -> one per thread
        {
            const int row = tid >> 2, cc = tid & 3;
            cp16(abase + row * LDA_B + cc * 16,
                 &Asrc[(size_t)(m0 + row) * Isz + k0 + cc * 8]);
        }
        // B: 128 rows x 4 cp16 = 512 -> two per thread
#pragma unroll
        for (int i = 0; i < 2; ++i) {
            const int idx = i * 256 + tid;
            const int row = idx >> 2, cc = idx & 3;
            cp16(bbase + row * LDA_B + cc * 16,
                 &Bsrc[(size_t)(n0 + row) * Isz + k0 + cc * 8]);
        }
        cp_commit();
    };

    // prologue
    load_chunk(0); load_chunk(1); load_chunk(2);

    for (int j = 0; j < NCHUNK; ++j) {
        if (j + 3 < NCHUNK) { load_chunk(j + 3); cp_wait<3>(); }
        else if (j == NCHUNK - 3) cp_wait<2>();
        else if (j == NCHUNK - 2) cp_wait<1>();
        else                      cp_wait<0>();
        __syncthreads();

        const uint32_t abase = sb + (j & (NSTAGE - 1)) * STAGE_B;
        const uint32_t bbase = abase + A_TILE_B;
#pragma unroll
        for (int k16 = 0; k16 < 2; ++k16) {
            const uint32_t kbyte = (uint32_t)(k16 * 16 + ((lane >> 4) << 3)) * 2;
            uint32_t af[2][4], bf[2][4];
#pragma unroll
            for (int mt = 0; mt < 2; ++mt) {
                const uint32_t addr =
                    abase + (wm_off + mt * 16 + (lane & 15)) * LDA_B + kbyte;
                LDSM_X4(af[mt][0], af[mt][1], af[mt][2], af[mt][3], addr);
            }
#pragma unroll
            for (int nt2 = 0; nt2 < 2; ++nt2) {
                const uint32_t addr =
                    bbase + (wn_off + nt2 * 16 + (lane & 15)) * LDA_B + kbyte;
                LDSM_X4(bf[nt2][0], bf[nt2][1], bf[nt2][2], bf[nt2][3], addr);
            }
#pragma unroll
            for (int mt = 0; mt < 2; ++mt)
#pragma unroll
                for (int nt = 0; nt < 4; ++nt) {
                    const int g = nt >> 1, w = nt & 1;
                    MMA_BF16(acc[mt][nt], af[mt], bf[g][w], bf[g][2 + w]);
                }
        }
        __syncthreads();
    }

    // epilogue: write g_cur with bias
#pragma unroll
    for (int mt = 0; mt < 2; ++mt) {
#pragma unroll
        for (int nt = 0; nt < 4; ++nt) {
            const int col = n0 + wn_off + nt * 8 + (lane & 3) * 2;
            const float2 bia = *reinterpret_cast<const float2*>(&b_in[col]);
            const int r0 = m0 + wm_off + mt * 16 + (lane >> 2);
            float2 v0, v1;
            v0.x = acc[mt][nt][0] + bia.x;
            v0.y = acc[mt][nt][1] + bia.y;
            v1.x = acc[mt][nt][2] + bia.x;
            v1.y = acc[mt][nt][3] + bia.y;
            *reinterpret_cast<float2*>(&g_cur[(size_t)r0 * Hsz + col]) = v0;
            *reinterpret_cast<float2*>(&g_cur[(size_t)(r0 + 8) * Hsz + col]) = v1;
        }
    }
}

// ---------------------------------------------------------------------------
// 4) LIF scan over T, per neuron h
// ---------------------------------------------------------------------------
__global__ void scan_kernel(const float* __restrict__ m0) {
    const int h = blockIdx.x * blockDim.x + threadIdx.x;
    if (h >= Hsz) return;
    float m = m0[h];
    float s = 0.f;
#pragma unroll 4
    for (int t = 0; t < T; ++t) {
        m = DECAY * m + g_cur[(size_t)t * Hsz + h];
        if (m > THRESHOLD) { s += 1.0f; m = 0.0f; }
    }
    g_agg[h] = s * (1.0f / (float)T);
}

// ---------------------------------------------------------------------------
// 5) Output GEMV
// ---------------------------------------------------------------------------
__global__ void out_init_kernel(float* __restrict__ out,
                                const float* __restrict__ b_out) {
    const int o = blockIdx.x * blockDim.x + threadIdx.x;
    if (o < Osz) out[o] = b_out[o];
}

#define OUT_OB 128
#define OUT_HB 256

__global__ __launch_bounds__(OUT_OB) void out_gemv_kernel(
    const float* __restrict__ W_out, float* __restrict__ out)
{
    __shared__ float s_agg[OUT_HB];
    const int obase = blockIdx.x * OUT_OB;
    const int hbase = blockIdx.y * OUT_HB;
    const int tid   = threadIdx.x;

    for (int i = tid; i < OUT_HB; i += OUT_OB)
        s_agg[i] = g_agg[hbase + i];
    __syncthreads();

    const int o = obase + tid;
    float acc = 0.f;
#pragma unroll 8
    for (int hh = 0; hh < OUT_HB; ++hh)
        acc += s_agg[hh] * W_out[(size_t)(hbase + hh) * Osz + o];
    atomicAdd(&out[o], acc);
}

// ---------------------------------------------------------------------------
extern "C" void kernel_launch(void* const* d_in, const int* in_sizes, int n_in,
                              void* d_out, int out_size) {
    const float* x     = (const float*)d_in[0];  // [B,T,I]
    const float* W_in  = (const float*)d_in[1];  // [I,H]
    const float* b_in  = (const float*)d_in[2];  // [H]
    const float* W_out = (const float*)d_in[3];  // [H,O]
    const float* b_out = (const float*)d_in[4];  // [O]
    const float* m0    = (const float*)d_in[5];  // [H]
    float* out = (float*)d_out;                  // [O]

    // 1) batch reduce + A bf16 split
    reduce_convert_A<<<(T * Isz / 4 + 255) / 256, 256>>>(x);

    // 2) W_in transpose + bf16 split
    dim3 tg(Hsz / 32, Isz / 32);
    transpose_convert_B<<<tg, dim3(32, 8)>>>(W_in);

    // 3) HMMA tensor-core GEMM: grid (4096/128, 256/64) = (32, 4) = 128 CTAs
    static int smem_set = 0;
    if (!smem_set) {
        cudaFuncSetAttribute(gemm_hmma,
                             cudaFuncAttributeMaxDynamicSharedMemorySize,
                             GEMM_SMEM);
        smem_set = 1;
    }
    dim3 gg(Hsz / 128, T / 64);
    gemm_hmma<<<gg, 256, GEMM_SMEM>>>(b_in);

    // 4) scan
    scan_kernel<<<(Hsz + 255) / 256, 256>>>(m0);

    // 5) output GEMV
    out_init_kernel<<<(Osz + 255) / 256, 256>>>(out, b_out);
    dim3 g4(Osz / OUT_OB, Hsz / OUT_HB);
    out_gemv_kernel<<<g4, OUT_OB>>>(W_out, out);
}

// round 4
// speedup vs baseline: 1.6774x; 1.2296x over previous
#include <cuda_runtime.h>
#include <cuda_bf16.h>
#include <cstdint>

#define Bsz 64
#define T   256
#define Isz 2048
#define Hsz 4096
#define Osz 1024

#define THRESHOLD 1.0f
#define DECAY     0.9f

// ---------------- scratch (device globals; no allocation allowed) ----------
__device__ __nv_bfloat16 g_Ahi[T * Isz];     // 1 MB
__device__ __nv_bfloat16 g_Alo[T * Isz];     // 1 MB
__device__ __nv_bfloat16 g_Bhi[Hsz * Isz];   // 16 MB  [N=4096][K=2048] K-major
__device__ __nv_bfloat16 g_Blo[Hsz * Isz];   // 16 MB
__device__ float g_cur[T * Hsz];             // 4 MB
__device__ float g_agg[Hsz];

// ---------------- PTX helpers ----------------------------------------------
__device__ __forceinline__ uint32_t smem_u32(const void* p) {
    uint32_t a;
    asm("{ .reg .u64 t; cvta.to.shared.u64 t, %1; cvt.u32.u64 %0, t; }"
        : "=r"(a) : "l"(p));
    return a;
}
__device__ __forceinline__ void cp16(uint32_t dst, const void* src) {
    asm volatile("cp.async.cg.shared.global [%0], [%1], 16;" :: "r"(dst), "l"(src));
}
__device__ __forceinline__ void cp_commit() {
    asm volatile("cp.async.commit_group;" ::: "memory");
}
template <int N> __device__ __forceinline__ void cp_wait() {
    asm volatile("cp.async.wait_group %0;" :: "n"(N) : "memory");
}
#define LDSM_X4(r0, r1, r2, r3, addr) \
    asm volatile("ldmatrix.sync.aligned.m8n8.x4.shared.b16 {%0,%1,%2,%3}, [%4];" \
                 : "=r"(r0), "=r"(r1), "=r"(r2), "=r"(r3) : "r"(addr))
#define MMA_BF16(d, a, b0, b1) \
    asm volatile("mma.sync.aligned.m16n8k16.row.col.f32.bf16.bf16.f32 " \
                 "{%0,%1,%2,%3}, {%4,%5,%6,%7}, {%8,%9}, {%0,%1,%2,%3};" \
                 : "+f"((d)[0]), "+f"((d)[1]), "+f"((d)[2]), "+f"((d)[3]) \
                 : "r"((a)[0]), "r"((a)[1]), "r"((a)[2]), "r"((a)[3]), \
                   "r"(b0), "r"(b1))

// ---------------------------------------------------------------------------
// 1) Batch reduce + bf16 hi/lo split: A = mean_b x[b,t,i] -> g_Ahi/g_Alo
// ---------------------------------------------------------------------------
__global__ void reduce_convert_A(const float* __restrict__ x) {
    const int idx = blockIdx.x * blockDim.x + threadIdx.x;  // over T*I/4
    const int n4  = (T * Isz) / 4;
    if (idx >= n4) return;
    const float4* __restrict__ x4 = reinterpret_cast<const float4*>(x);
    float a[4] = {0.f, 0.f, 0.f, 0.f};
#pragma unroll 8
    for (int b = 0; b < Bsz; ++b) {
        float4 v = x4[(size_t)b * n4 + idx];
        a[0] += v.x; a[1] += v.y; a[2] += v.z; a[3] += v.w;
    }
    const float s = 1.0f / (float)Bsz;
    const int base = idx * 4;
#pragma unroll
    for (int i = 0; i < 4; ++i) {
        float v = a[i] * s;
        __nv_bfloat16 hi = __float2bfloat16(v);
        float rem = v - __bfloat162float(hi);
        g_Ahi[base + i] = hi;
        g_Alo[base + i] = __float2bfloat16(rem);
    }
}

// ---------------------------------------------------------------------------
// 2) Transpose + convert W_in [I,H] fp32 -> B_hi/B_lo [H,I] bf16 (K-major)
// ---------------------------------------------------------------------------
__global__ void transpose_convert_B(const float* __restrict__ W) {
    __shared__ float s[32][33];
    const int i0 = blockIdx.y * 32;  // k (row of W)
    const int h0 = blockIdx.x * 32;  // n (col of W)
    const int tx = threadIdx.x;      // 0..31
    const int ty = threadIdx.y;      // 0..7
#pragma unroll
    for (int j = 0; j < 4; ++j) {
        int r = ty + j * 8;
        s[r][tx] = W[(size_t)(i0 + r) * Hsz + h0 + tx];
    }
    __syncthreads();
#pragma unroll
    for (int j = 0; j < 4; ++j) {
        int r = ty + j * 8;          // n offset
        float v = s[tx][r];          // = W[i0+tx][h0+r]
        __nv_bfloat16 hi = __float2bfloat16(v);
        float rem = v - __bfloat162float(hi);
        size_t o = (size_t)(h0 + r) * Isz + i0 + tx;
        g_Bhi[o] = hi;
        g_Blo[o] = __float2bfloat16(rem);
    }
}

// ---------------------------------------------------------------------------
// 3) HMMA bf16 GEMM (3-pass hi/lo): cur[256,4096] = A @ B^T + b_in
//    CTA 64(M)x128(N), 8 warps of 32x32, BK=64, 3-stage cp.async pipeline.
// ---------------------------------------------------------------------------
#define LDA_B 144                    // 64 bf16 (128B) + 16B pad row stride
#define A_TILE_B (64 * LDA_B)        // 9216
#define B_TILE_B (128 * LDA_B)       // 18432
#define STAGE_B  (A_TILE_B + B_TILE_B)   // 27648
#define NSTAGE 3
#define GEMM_SMEM (NSTAGE * STAGE_B)     // 82944
#define NCHUNK 96                    // 3 passes * (2048/64)

__global__ __launch_bounds__(256, 1) void gemm_hmma(const float* __restrict__ b_in) {
    extern __shared__ char smem[];
    const uint32_t sb = smem_u32(smem);
    const int tid  = threadIdx.x;
    const int lane = tid & 31;
    const int wid  = tid >> 5;
    const int m0 = blockIdx.y * 64;
    const int n0 = blockIdx.x * 128;

    const int wm_off = (wid & 1) * 32;   // warp m offset (0/32)
    const int wn_off = (wid >> 1) * 32;  // warp n offset (0/32/64/96)

    float acc[2][4][4];
#pragma unroll
    for (int i = 0; i < 2; ++i)
#pragma unroll
        for (int j = 0; j < 4; ++j)
#pragma unroll
            for (int k = 0; k < 4; ++k) acc[i][j][k] = 0.f;

    auto stage_base = [&](int c) -> uint32_t {
        return sb + (uint32_t)(c % NSTAGE) * STAGE_B;
    };

    auto load_chunk = [&](int c) {
        const int p  = c >> 5;           // pass 0..2
        const int k0 = (c & 31) << 6;    // k offset (64 per chunk)
        const __nv_bfloat16* __restrict__ Asrc = (p == 1) ? g_Alo : g_Ahi;
        const __nv_bfloat16* __restrict__ Bsrc = (p == 2) ? g_Blo : g_Bhi;
        const uint32_t abase = stage_base(c);
        const uint32_t bbase = abase + A_TILE_B;
        // A: 64 rows x 8 cp16 = 512 -> two per thread
#pragma unroll
        for (int i = 0; i < 2; ++i) {
            const int idx = i * 256 + tid;
            const int row = idx >> 3, cc = idx & 7;
            cp16(abase + row * LDA_B + cc * 16,
                 &Asrc[(size_t)(m0 + row) * Isz + k0 + cc * 8]);
        }
        // B: 128 rows x 8 cp16 = 1024 -> four per thread
#pragma unroll
        for (int i = 0; i < 4; ++i) {
            const int idx = i * 256 + tid;
            const int row = idx >> 3, cc = idx & 7;
            cp16(bbase + row * LDA_B + cc * 16,
                 &Bsrc[(size_t)(n0 + row) * Isz + k0 + cc * 8]);
        }
        cp_commit();
    };

    // prologue: 2 chunks in flight
    load_chunk(0); load_chunk(1);

    for (int j = 0; j < NCHUNK; ++j) {
        if (j + 2 < NCHUNK) { load_chunk(j + 2); cp_wait<2>(); }
        else if (j == NCHUNK - 2) cp_wait<1>();
        else                      cp_wait<0>();
        __syncthreads();

        const uint32_t abase = stage_base(j);
        const uint32_t bbase = abase + A_TILE_B;
#pragma unroll
        for (int k16 = 0; k16 < 4; ++k16) {
            const uint32_t kbyte = (uint32_t)(k16 * 16 + ((lane >> 4) << 3)) * 2;
            uint32_t af[2][4], bf[2][4];
#pragma unroll
            for (int mt = 0; mt < 2; ++mt) {
                const uint32_t addr =
                    abase + (wm_off + mt * 16 + (lane & 15)) * LDA_B + kbyte;
                LDSM_X4(af[mt][0], af[mt][1], af[mt][2], af[mt][3], addr);
            }
#pragma unroll
            for (int nt2 = 0; nt2 < 2; ++nt2) {
                const uint32_t addr =
                    bbase + (wn_off + nt2 * 16 + (lane & 15)) * LDA_B + kbyte;
                LDSM_X4(bf[nt2][0], bf[nt2][1], bf[nt2][2], bf[nt2][3], addr);
            }
#pragma unroll
            for (int mt = 0; mt < 2; ++mt)
#pragma unroll
                for (int nt = 0; nt < 4; ++nt) {
                    const int g = nt >> 1, w = nt & 1;
                    MMA_BF16(acc[mt][nt], af[mt], bf[g][w], bf[g][2 + w]);
                }
        }
        __syncthreads();
    }

    // epilogue: write g_cur with bias
#pragma unroll
    for (int mt = 0; mt < 2; ++mt) {
#pragma unroll
        for (int nt = 0; nt < 4; ++nt) {
            const int col = n0 + wn_off + nt * 8 + (lane & 3) * 2;
            const float2 bia = *reinterpret_cast<const float2*>(&b_in[col]);
            const int r0 = m0 + wm_off + mt * 16 + (lane >> 2);
            float2 v0, v1;
            v0.x = acc[mt][nt][0] + bia.x;
            v0.y = acc[mt][nt][1] + bia.y;
            v1.x = acc[mt][nt][2] + bia.x;
            v1.y = acc[mt][nt][3] + bia.y;
            *reinterpret_cast<float2*>(&g_cur[(size_t)r0 * Hsz + col]) = v0;
            *reinterpret_cast<float2*>(&g_cur[(size_t)(r0 + 8) * Hsz + col]) = v1;
        }
    }
}

// ---------------------------------------------------------------------------
// 4) LIF scan over T. One warp per block, 128 blocks, 16-deep load batches
//    to maximize memory-level parallelism (g_cur is L2-resident, ~240cyc).
// ---------------------------------------------------------------------------
__global__ __launch_bounds__(32) void scan_kernel(const float* __restrict__ m0) {
    const int h = blockIdx.x * 32 + threadIdx.x;
    float m = m0[h];
    float s = 0.f;
    for (int t0 = 0; t0 < T; t0 += 16) {
        float buf[16];
#pragma unroll
        for (int i = 0; i < 16; ++i)
            buf[i] = __ldg(&g_cur[(size_t)(t0 + i) * Hsz + h]);
#pragma unroll
        for (int i = 0; i < 16; ++i) {
            m = DECAY * m + buf[i];
            if (m > THRESHOLD) { s += 1.0f; m = 0.0f; }
        }
    }
    g_agg[h] = s * (1.0f / (float)T);
}

// ---------------------------------------------------------------------------
// 5) Output GEMV
// ---------------------------------------------------------------------------
__global__ void out_init_kernel(float* __restrict__ out,
                                const float* __restrict__ b_out) {
    const int o = blockIdx.x * blockDim.x + threadIdx.x;
    if (o < Osz) out[o] = b_out[o];
}

#define OUT_OB 128
#define OUT_HB 256

__global__ __launch_bounds__(OUT_OB) void out_gemv_kernel(
    const float* __restrict__ W_out, float* __restrict__ out)
{
    __shared__ float s_agg[OUT_HB];
    const int obase = blockIdx.x * OUT_OB;
    const int hbase = blockIdx.y * OUT_HB;
    const int tid   = threadIdx.x;

    for (int i = tid; i < OUT_HB; i += OUT_OB)
        s_agg[i] = g_agg[hbase + i];
    __syncthreads();

    const int o = obase + tid;
    float acc = 0.f;
#pragma unroll 8
    for (int hh = 0; hh < OUT_HB; ++hh)
        acc += s_agg[hh] * W_out[(size_t)(hbase + hh) * Osz + o];
    atomicAdd(&out[o], acc);
}

// ---------------------------------------------------------------------------
extern "C" void kernel_launch(void* const* d_in, const int* in_sizes, int n_in,
                              void* d_out, int out_size) {
    const float* x     = (const float*)d_in[0];  // [B,T,I]
    const float* W_in  = (const float*)d_in[1];  // [I,H]
    const float* b_in  = (const float*)d_in[2];  // [H]
    const float* W_out = (const float*)d_in[3];  // [H,O]
    const float* b_out = (const float*)d_in[4];  // [O]
    const float* m0    = (const float*)d_in[5];  // [H]
    float* out = (float*)d_out;                  // [O]

    // 1) batch reduce + A bf16 split
    reduce_convert_A<<<(T * Isz / 4 + 255) / 256, 256>>>(x);

    // 2) W_in transpose + bf16 split
    dim3 tg(Hsz / 32, Isz / 32);
    transpose_convert_B<<<tg, dim3(32, 8)>>>(W_in);

    // 3) HMMA tensor-core GEMM: grid (4096/128, 256/64) = (32, 4) = 128 CTAs
    cudaFuncSetAttribute(gemm_hmma,
                         cudaFuncAttributeMaxDynamicSharedMemorySize,
                         GEMM_SMEM);
    dim3 gg(Hsz / 128, T / 64);
    gemm_hmma<<<gg, 256, GEMM_SMEM>>>(b_in);

    // 4) scan: 128 blocks x 32 threads
    scan_kernel<<<Hsz / 32, 32>>>(m0);

    // 5) output GEMV
    out_init_kernel<<<(Osz + 255) / 256, 256>>>(out, b_out);
    dim3 g4(Osz / OUT_OB, Hsz / OUT_HB);
    out_gemv_kernel<<<g4, OUT_OB>>>(W_out, out);
}

// round 5
// speedup vs baseline: 1.8490x; 1.1023x over previous
#include <cuda_runtime.h>
#include <cuda_bf16.h>
#include <cstdint>

#define Bsz 64
#define T   256
#define Isz 2048
#define Hsz 4096
#define Osz 1024

#define THRESHOLD 1.0f
#define DECAY     0.9f

// ---------------- scratch (device globals; no allocation allowed) ----------
__device__ __nv_bfloat16 g_Ahi[T * Isz];     // 1 MB
__device__ __nv_bfloat16 g_Alo[T * Isz];     // 1 MB
__device__ __nv_bfloat16 g_Bhi[Hsz * Isz];   // 16 MB  [N=4096][K=2048] K-major
__device__ __nv_bfloat16 g_Blo[Hsz * Isz];   // 16 MB
__device__ float g_cur[T * Hsz];             // 4 MB
__device__ float g_agg[Hsz];

// ---------------- PTX helpers ----------------------------------------------
__device__ __forceinline__ uint32_t smem_u32(const void* p) {
    uint32_t a;
    asm("{ .reg .u64 t; cvta.to.shared.u64 t, %1; cvt.u32.u64 %0, t; }"
        : "=r"(a) : "l"(p));
    return a;
}
__device__ __forceinline__ void cp16(uint32_t dst, const void* src) {
    asm volatile("cp.async.cg.shared.global [%0], [%1], 16;" :: "r"(dst), "l"(src));
}
__device__ __forceinline__ void cp_commit() {
    asm volatile("cp.async.commit_group;" ::: "memory");
}
template <int N> __device__ __forceinline__ void cp_wait() {
    asm volatile("cp.async.wait_group %0;" :: "n"(N) : "memory");
}
#define LDSM_X4(r0, r1, r2, r3, addr) \
    asm volatile("ldmatrix.sync.aligned.m8n8.x4.shared.b16 {%0,%1,%2,%3}, [%4];" \
                 : "=r"(r0), "=r"(r1), "=r"(r2), "=r"(r3) : "r"(addr))
#define MMA_BF16(d, a, b0, b1) \
    asm volatile("mma.sync.aligned.m16n8k16.row.col.f32.bf16.bf16.f32 " \
                 "{%0,%1,%2,%3}, {%4,%5,%6,%7}, {%8,%9}, {%0,%1,%2,%3};" \
                 : "+f"((d)[0]), "+f"((d)[1]), "+f"((d)[2]), "+f"((d)[3]) \
                 : "r"((a)[0]), "r"((a)[1]), "r"((a)[2]), "r"((a)[3]), \
                   "r"(b0), "r"(b1))

// ---------------------------------------------------------------------------
// 1) Merged prep: blocks [0,512) batch-reduce x -> A hi/lo;
//    blocks [512, 512+8192) transpose+convert W_in -> B hi/lo.
//    Both HBM-bound; merging overlaps their DRAM phases.
// ---------------------------------------------------------------------------
#define RED_BLOCKS 512
__global__ __launch_bounds__(256) void prep_kernel(const float* __restrict__ x,
                                                   const float* __restrict__ W) {
    if (blockIdx.x < RED_BLOCKS) {
        const int idx = blockIdx.x * 256 + threadIdx.x;  // over T*I/4
        const int n4  = (T * Isz) / 4;
        const float4* __restrict__ x4 = reinterpret_cast<const float4*>(x);
        float a[4] = {0.f, 0.f, 0.f, 0.f};
#pragma unroll 8
        for (int b = 0; b < Bsz; ++b) {
            float4 v = x4[(size_t)b * n4 + idx];
            a[0] += v.x; a[1] += v.y; a[2] += v.z; a[3] += v.w;
        }
        const float s = 1.0f / (float)Bsz;
        const int base = idx * 4;
#pragma unroll
        for (int i = 0; i < 4; ++i) {
            float v = a[i] * s;
            __nv_bfloat16 hi = __float2bfloat16(v);
            float rem = v - __bfloat162float(hi);
            g_Ahi[base + i] = hi;
            g_Alo[base + i] = __float2bfloat16(rem);
        }
    } else {
        __shared__ float s[32][33];
        const int bid = blockIdx.x - RED_BLOCKS;
        const int h0 = (bid & 127) * 32;   // n tile
        const int i0 = (bid >> 7) * 32;    // k tile
        const int tx = threadIdx.x & 31;
        const int ty = threadIdx.x >> 5;   // 0..7
#pragma unroll
        for (int j = 0; j < 4; ++j) {
            int r = ty + j * 8;
            s[r][tx] = W[(size_t)(i0 + r) * Hsz + h0 + tx];
        }
        __syncthreads();
#pragma unroll
        for (int j = 0; j < 4; ++j) {
            int r = ty + j * 8;          // n offset
            float v = s[tx][r];          // = W[i0+tx][h0+r]
            __nv_bfloat16 hi = __float2bfloat16(v);
            float rem = v - __bfloat162float(hi);
            size_t o = (size_t)(h0 + r) * Isz + i0 + tx;
            g_Bhi[o] = hi;
            g_Blo[o] = __float2bfloat16(rem);
        }
    }
}

// ---------------------------------------------------------------------------
// 2) HMMA bf16 GEMM (3-pass hi/lo): cur[256,4096] = A @ B^T + b_in
//    CTA 64(M)x128(N), 8 warps of 32x32, BK=128, 3-stage cp.async pipeline.
// ---------------------------------------------------------------------------
#define LDA_B 272                    // 128 bf16 (256B) + 16B pad row stride
#define A_TILE_B (64 * LDA_B)        // 17408
#define B_TILE_B (128 * LDA_B)       // 34816
#define STAGE_B  (A_TILE_B + B_TILE_B)   // 52224
#define NSTAGE 3
#define GEMM_SMEM (NSTAGE * STAGE_B)     // 156672
#define NCHUNK 48                    // 3 passes * (2048/128)

__global__ __launch_bounds__(256, 1) void gemm_hmma(const float* __restrict__ b_in) {
    extern __shared__ char smem[];
    const uint32_t sb = smem_u32(smem);
    const int tid  = threadIdx.x;
    const int lane = tid & 31;
    const int wid  = tid >> 5;
    const int m0 = blockIdx.y * 64;
    const int n0 = blockIdx.x * 128;

    const int wm_off = (wid & 1) * 32;   // warp m offset (0/32)
    const int wn_off = (wid >> 1) * 32;  // warp n offset (0/32/64/96)

    float acc[2][4][4];
#pragma unroll
    for (int i = 0; i < 2; ++i)
#pragma unroll
        for (int j = 0; j < 4; ++j)
#pragma unroll
            for (int k = 0; k < 4; ++k) acc[i][j][k] = 0.f;

    auto stage_base = [&](int c) -> uint32_t {
        return sb + (uint32_t)(c % NSTAGE) * STAGE_B;
    };

    auto load_chunk = [&](int c) {
        const int p  = c >> 4;           // pass 0..2 (16 chunks each)
        const int k0 = (c & 15) << 7;    // k offset (128 per chunk)
        const __nv_bfloat16* __restrict__ Asrc = (p == 1) ? g_Alo : g_Ahi;
        const __nv_bfloat16* __restrict__ Bsrc = (p == 2) ? g_Blo : g_Bhi;
        const uint32_t abase = stage_base(c);
        const uint32_t bbase = abase + A_TILE_B;
        // A: 64 rows x 16 cp16 = 1024 -> four per thread
#pragma unroll
        for (int i = 0; i < 4; ++i) {
            const int idx = i * 256 + tid;
            const int row = idx >> 4, cc = idx & 15;
            cp16(abase + row * LDA_B + cc * 16,
                 &Asrc[(size_t)(m0 + row) * Isz + k0 + cc * 8]);
        }
        // B: 128 rows x 16 cp16 = 2048 -> eight per thread
#pragma unroll
        for (int i = 0; i < 8; ++i) {
            const int idx = i * 256 + tid;
            const int row = idx >> 4, cc = idx & 15;
            cp16(bbase + row * LDA_B + cc * 16,
                 &Bsrc[(size_t)(n0 + row) * Isz + k0 + cc * 8]);
        }
        cp_commit();
    };

    // prologue: 2 chunks in flight
    load_chunk(0); load_chunk(1);

    for (int j = 0; j < NCHUNK; ++j) {
        if (j + 2 < NCHUNK) { load_chunk(j + 2); cp_wait<2>(); }
        else if (j == NCHUNK - 2) cp_wait<1>();
        else                      cp_wait<0>();
        __syncthreads();

        const uint32_t abase = stage_base(j);
        const uint32_t bbase = abase + A_TILE_B;
#pragma unroll
        for (int k16 = 0; k16 < 8; ++k16) {
            const uint32_t kbyte = (uint32_t)(k16 * 16 + ((lane >> 4) << 3)) * 2;
            uint32_t af[2][4], bf[2][4];
#pragma unroll
            for (int mt = 0; mt < 2; ++mt) {
                const uint32_t addr =
                    abase + (wm_off + mt * 16 + (lane & 15)) * LDA_B + kbyte;
                LDSM_X4(af[mt][0], af[mt][1], af[mt][2], af[mt][3], addr);
            }
#pragma unroll
            for (int nt2 = 0; nt2 < 2; ++nt2) {
                const uint32_t addr =
                    bbase + (wn_off + nt2 * 16 + (lane & 15)) * LDA_B + kbyte;
                LDSM_X4(bf[nt2][0], bf[nt2][1], bf[nt2][2], bf[nt2][3], addr);
            }
#pragma unroll
            for (int mt = 0; mt < 2; ++mt)
#pragma unroll
                for (int nt = 0; nt < 4; ++nt) {
                    const int g = nt >> 1, w = nt & 1;
                    MMA_BF16(acc[mt][nt], af[mt], bf[g][w], bf[g][2 + w]);
                }
        }
        __syncthreads();
    }

    // epilogue: write g_cur with bias
#pragma unroll
    for (int mt = 0; mt < 2; ++mt) {
#pragma unroll
        for (int nt = 0; nt < 4; ++nt) {
            const int col = n0 + wn_off + nt * 8 + (lane & 3) * 2;
            const float2 bia = *reinterpret_cast<const float2*>(&b_in[col]);
            const int r0 = m0 + wm_off + mt * 16 + (lane >> 2);
            float2 v0, v1;
            v0.x = acc[mt][nt][0] + bia.x;
            v0.y = acc[mt][nt][1] + bia.y;
            v1.x = acc[mt][nt][2] + bia.x;
            v1.y = acc[mt][nt][3] + bia.y;
            *reinterpret_cast<float2*>(&g_cur[(size_t)r0 * Hsz + col]) = v0;
            *reinterpret_cast<float2*>(&g_cur[(size_t)(r0 + 8) * Hsz + col]) = v1;
        }
    }
}

// ---------------------------------------------------------------------------
// 3) LIF scan: 128 blocks x 32 threads, software-pipelined 16-deep prefetch.
//    Also initializes out[] = b_out[] (blocks 0..31) ahead of the GEMV.
// ---------------------------------------------------------------------------
__global__ __launch_bounds__(32) void scan_kernel(const float* __restrict__ m0,
                                                  float* __restrict__ out,
                                                  const float* __restrict__ b_out) {
    const int h = blockIdx.x * 32 + threadIdx.x;
    if (blockIdx.x < Osz / 32) out[h] = b_out[h];

    float m = m0[h];
    float s = 0.f;
    float buf[2][16];
#pragma unroll
    for (int i = 0; i < 16; ++i)
        buf[0][i] = __ldg(&g_cur[(size_t)i * Hsz + h]);

#pragma unroll
    for (int t0 = 0; t0 < T; t0 += 16) {
        const int cur = (t0 >> 4) & 1;
        const int nxt = cur ^ 1;
        if (t0 + 16 < T) {
#pragma unroll
            for (int i = 0; i < 16; ++i)
                buf[nxt][i] = __ldg(&g_cur[(size_t)(t0 + 16 + i) * Hsz + h]);
        }
#pragma unroll
        for (int i = 0; i < 16; ++i) {
            m = DECAY * m + buf[cur][i];
            if (m > THRESHOLD) { s += 1.0f; m = 0.0f; }
        }
    }
    g_agg[h] = s * (1.0f / (float)T);
}

// ---------------------------------------------------------------------------
// 4) Output GEMV (out pre-initialized with bias by scan_kernel)
// ---------------------------------------------------------------------------
#define OUT_OB 128
#define OUT_HB 256

__global__ __launch_bounds__(OUT_OB) void out_gemv_kernel(
    const float* __restrict__ W_out, float* __restrict__ out)
{
    __shared__ float s_agg[OUT_HB];
    const int obase = blockIdx.x * OUT_OB;
    const int hbase = blockIdx.y * OUT_HB;
    const int tid   = threadIdx.x;

    for (int i = tid; i < OUT_HB; i += OUT_OB)
        s_agg[i] = g_agg[hbase + i];
    __syncthreads();

    const int o = obase + tid;
    float acc = 0.f;
#pragma unroll 8
    for (int hh = 0; hh < OUT_HB; ++hh)
        acc += s_agg[hh] * W_out[(size_t)(hbase + hh) * Osz + o];
    atomicAdd(&out[o], acc);
}

// ---------------------------------------------------------------------------
extern "C" void kernel_launch(void* const* d_in, const int* in_sizes, int n_in,
                              void* d_out, int out_size) {
    const float* x     = (const float*)d_in[0];  // [B,T,I]
    const float* W_in  = (const float*)d_in[1];  // [I,H]
    const float* b_in  = (const float*)d_in[2];  // [H]
    const float* W_out = (const float*)d_in[3];  // [H,O]
    const float* b_out = (const float*)d_in[4];  // [O]
    const float* m0    = (const float*)d_in[5];  // [H]
    float* out = (float*)d_out;                  // [O]

    // 1) merged reduce + transpose/convert
    prep_kernel<<<RED_BLOCKS + (Hsz / 32) * (Isz / 32), 256>>>(x, W_in);

    // 2) HMMA tensor-core GEMM: grid (4096/128, 256/64) = (32, 4) = 128 CTAs
    cudaFuncSetAttribute(gemm_hmma,
                         cudaFuncAttributeMaxDynamicSharedMemorySize,
                         GEMM_SMEM);
    dim3 gg(Hsz / 128, T / 64);
    gemm_hmma<<<gg, 256, GEMM_SMEM>>>(b_in);

    // 3) scan (+ output bias init): 128 blocks x 32 threads
    scan_kernel<<<Hsz / 32, 32>>>(m0, out, b_out);

    // 4) output GEMV
    dim3 g4(Osz / OUT_OB, Hsz / OUT_HB);
    out_gemv_kernel<<<g4, OUT_OB>>>(W_out, out);
}

// round 6
// speedup vs baseline: 2.1274x; 1.1506x over previous
#include <cuda_runtime.h>
#include <cuda_bf16.h>
#include <cstdint>

#define Bsz 64
#define T   256
#define Isz 2048
#define Hsz 4096
#define Osz 1024

#define THRESHOLD 1.0f
#define DECAY     0.9f

// ---------------- scratch (device globals; no allocation allowed) ----------
__device__ __nv_bfloat16 g_Ahi[T * Isz];     // 1 MB
__device__ __nv_bfloat16 g_Alo[T * Isz];     // 1 MB
__device__ __nv_bfloat16 g_Bhi[Hsz * Isz];   // 16 MB  [N=4096][K=2048] K-major
__device__ __nv_bfloat16 g_Blo[Hsz * Isz];   // 16 MB
__device__ float g_cur[T * Hsz];             // 4 MB
__device__ float g_agg[Hsz];

// ---------------- PTX helpers ----------------------------------------------
__device__ __forceinline__ uint32_t smem_u32(const void* p) {
    uint32_t a;
    asm("{ .reg .u64 t; cvta.to.shared.u64 t, %1; cvt.u32.u64 %0, t; }"
        : "=r"(a) : "l"(p));
    return a;
}
__device__ __forceinline__ void cp16(uint32_t dst, const void* src) {
    asm volatile("cp.async.cg.shared.global [%0], [%1], 16;" :: "r"(dst), "l"(src));
}
__device__ __forceinline__ void cp_commit() {
    asm volatile("cp.async.commit_group;" ::: "memory");
}
template <int N> __device__ __forceinline__ void cp_wait() {
    asm volatile("cp.async.wait_group %0;" :: "n"(N) : "memory");
}
#define LDSM_X4(r0, r1, r2, r3, addr) \
    asm volatile("ldmatrix.sync.aligned.m8n8.x4.shared.b16 {%0,%1,%2,%3}, [%4];" \
                 : "=r"(r0), "=r"(r1), "=r"(r2), "=r"(r3) : "r"(addr))
#define MMA_BF16(d, a, b0, b1) \
    asm volatile("mma.sync.aligned.m16n8k16.row.col.f32.bf16.bf16.f32 " \
                 "{%0,%1,%2,%3}, {%4,%5,%6,%7}, {%8,%9}, {%0,%1,%2,%3};" \
                 : "+f"((d)[0]), "+f"((d)[1]), "+f"((d)[2]), "+f"((d)[3]) \
                 : "r"((a)[0]), "r"((a)[1]), "r"((a)[2]), "r"((a)[3]), \
                   "r"(b0), "r"(b1))

// ---------------------------------------------------------------------------
// 1) Merged prep: blocks [0,512) batch-reduce x -> A hi/lo;
//    blocks [512, 512+8192) transpose+convert W_in -> B hi/lo.
// ---------------------------------------------------------------------------
#define RED_BLOCKS 512
__global__ __launch_bounds__(256) void prep_kernel(const float* __restrict__ x,
                                                   const float* __restrict__ W) {
    if (blockIdx.x < RED_BLOCKS) {
        const int idx = blockIdx.x * 256 + threadIdx.x;  // over T*I/4
        const int n4  = (T * Isz) / 4;
        const float4* __restrict__ x4 = reinterpret_cast<const float4*>(x);
        float a[4] = {0.f, 0.f, 0.f, 0.f};
#pragma unroll 8
        for (int b = 0; b < Bsz; ++b) {
            float4 v = x4[(size_t)b * n4 + idx];
            a[0] += v.x; a[1] += v.y; a[2] += v.z; a[3] += v.w;
        }
        const float s = 1.0f / (float)Bsz;
        const int base = idx * 4;
#pragma unroll
        for (int i = 0; i < 4; ++i) {
            float v = a[i] * s;
            __nv_bfloat16 hi = __float2bfloat16(v);
            float rem = v - __bfloat162float(hi);
            g_Ahi[base + i] = hi;
            g_Alo[base + i] = __float2bfloat16(rem);
        }
    } else {
        __shared__ float s[32][33];
        const int bid = blockIdx.x - RED_BLOCKS;
        const int h0 = (bid & 127) * 32;   // n tile
        const int i0 = (bid >> 7) * 32;    // k tile
        const int tx = threadIdx.x & 31;
        const int ty = threadIdx.x >> 5;   // 0..7
#pragma unroll
        for (int j = 0; j < 4; ++j) {
            int r = ty + j * 8;
            s[r][tx] = W[(size_t)(i0 + r) * Hsz + h0 + tx];
        }
        __syncthreads();
#pragma unroll
        for (int j = 0; j < 4; ++j) {
            int r = ty + j * 8;          // n offset
            float v = s[tx][r];          // = W[i0+tx][h0+r]
            __nv_bfloat16 hi = __float2bfloat16(v);
            float rem = v - __bfloat162float(hi);
            size_t o = (size_t)(h0 + r) * Isz + i0 + tx;
            g_Bhi[o] = hi;
            g_Blo[o] = __float2bfloat16(rem);
        }
    }
}

// ---------------------------------------------------------------------------
// 2) HMMA bf16 GEMM (3-pass hi/lo): cur[256,4096] = A @ B^T + b_in
//    CTA 64(M)x128(N), 8 warps of 32x32, BK=128, 3-stage cp.async pipeline.
// ---------------------------------------------------------------------------
#define LDA_B 272                    // 128 bf16 (256B) + 16B pad row stride
#define A_TILE_B (64 * LDA_B)        // 17408
#define B_TILE_B (128 * LDA_B)       // 34816
#define STAGE_B  (A_TILE_B + B_TILE_B)   // 52224
#define NSTAGE 3
#define GEMM_SMEM (NSTAGE * STAGE_B)     // 156672
#define NCHUNK 48                    // 3 passes * (2048/128)

__global__ __launch_bounds__(256, 1) void gemm_hmma(const float* __restrict__ b_in) {
    extern __shared__ char smem[];
    const uint32_t sb = smem_u32(smem);
    const int tid  = threadIdx.x;
    const int lane = tid & 31;
    const int wid  = tid >> 5;
    const int m0 = blockIdx.y * 64;
    const int n0 = blockIdx.x * 128;

    const int wm_off = (wid & 1) * 32;   // warp m offset (0/32)
    const int wn_off = (wid >> 1) * 32;  // warp n offset (0/32/64/96)

    float acc[2][4][4];
#pragma unroll
    for (int i = 0; i < 2; ++i)
#pragma unroll
        for (int j = 0; j < 4; ++j)
#pragma unroll
            for (int k = 0; k < 4; ++k) acc[i][j][k] = 0.f;

    auto stage_base = [&](int c) -> uint32_t {
        return sb + (uint32_t)(c % NSTAGE) * STAGE_B;
    };

    auto load_chunk = [&](int c) {
        const int p  = c >> 4;           // pass 0..2 (16 chunks each)
        const int k0 = (c & 15) << 7;    // k offset (128 per chunk)
        const __nv_bfloat16* __restrict__ Asrc = (p == 1) ? g_Alo : g_Ahi;
        const __nv_bfloat16* __restrict__ Bsrc = (p == 2) ? g_Blo : g_Bhi;
        const uint32_t abase = stage_base(c);
        const uint32_t bbase = abase + A_TILE_B;
        // A: 64 rows x 16 cp16 = 1024 -> four per thread
#pragma unroll
        for (int i = 0; i < 4; ++i) {
            const int idx = i * 256 + tid;
            const int row = idx >> 4, cc = idx & 15;
            cp16(abase + row * LDA_B + cc * 16,
                 &Asrc[(size_t)(m0 + row) * Isz + k0 + cc * 8]);
        }
        // B: 128 rows x 16 cp16 = 2048 -> eight per thread
#pragma unroll
        for (int i = 0; i < 8; ++i) {
            const int idx = i * 256 + tid;
            const int row = idx >> 4, cc = idx & 15;
            cp16(bbase + row * LDA_B + cc * 16,
                 &Bsrc[(size_t)(n0 + row) * Isz + k0 + cc * 8]);
        }
        cp_commit();
    };

    // prologue: 2 chunks in flight
    load_chunk(0); load_chunk(1);

    for (int j = 0; j < NCHUNK; ++j) {
        if (j + 2 < NCHUNK) { load_chunk(j + 2); cp_wait<2>(); }
        else if (j == NCHUNK - 2) cp_wait<1>();
        else                      cp_wait<0>();
        __syncthreads();

        const uint32_t abase = stage_base(j);
        const uint32_t bbase = abase + A_TILE_B;
#pragma unroll
        for (int k16 = 0; k16 < 8; ++k16) {
            const uint32_t kbyte = (uint32_t)(k16 * 16 + ((lane >> 4) << 3)) * 2;
            uint32_t af[2][4], bf[2][4];
#pragma unroll
            for (int mt = 0; mt < 2; ++mt) {
                const uint32_t addr =
                    abase + (wm_off + mt * 16 + (lane & 15)) * LDA_B + kbyte;
                LDSM_X4(af[mt][0], af[mt][1], af[mt][2], af[mt][3], addr);
            }
#pragma unroll
            for (int nt2 = 0; nt2 < 2; ++nt2) {
                const uint32_t addr =
                    bbase + (wn_off + nt2 * 16 + (lane & 15)) * LDA_B + kbyte;
                LDSM_X4(bf[nt2][0], bf[nt2][1], bf[nt2][2], bf[nt2][3], addr);
            }
#pragma unroll
            for (int mt = 0; mt < 2; ++mt)
#pragma unroll
                for (int nt = 0; nt < 4; ++nt) {
                    const int g = nt >> 1, w = nt & 1;
                    MMA_BF16(acc[mt][nt], af[mt], bf[g][w], bf[g][2 + w]);
                }
        }
        __syncthreads();
    }

    // epilogue: write g_cur with bias
#pragma unroll
    for (int mt = 0; mt < 2; ++mt) {
#pragma unroll
        for (int nt = 0; nt < 4; ++nt) {
            const int col = n0 + wn_off + nt * 8 + (lane & 3) * 2;
            const float2 bia = *reinterpret_cast<const float2*>(&b_in[col]);
            const int r0 = m0 + wm_off + mt * 16 + (lane >> 2);
            float2 v0, v1;
            v0.x = acc[mt][nt][0] + bia.x;
            v0.y = acc[mt][nt][1] + bia.y;
            v1.x = acc[mt][nt][2] + bia.x;
            v1.y = acc[mt][nt][3] + bia.y;
            *reinterpret_cast<float2*>(&g_cur[(size_t)r0 * Hsz + col]) = v0;
            *reinterpret_cast<float2*>(&g_cur[(size_t)(r0 + 8) * Hsz + col]) = v1;
        }
    }
}

// ---------------------------------------------------------------------------
// 3) LIF scan: 128 blocks x 32 threads, software-pipelined 16-deep prefetch.
//    Also initializes out[] = b_out[] (blocks 0..31) ahead of the GEMV.
// ---------------------------------------------------------------------------
__global__ __launch_bounds__(32) void scan_kernel(const float* __restrict__ m0,
                                                  float* __restrict__ out,
                                                  const float* __restrict__ b_out) {
    const int h = blockIdx.x * 32 + threadIdx.x;
    if (blockIdx.x < Osz / 32) out[h] = b_out[h];

    float m = m0[h];
    float s = 0.f;
    float buf[2][16];
#pragma unroll
    for (int i = 0; i < 16; ++i)
        buf[0][i] = __ldg(&g_cur[(size_t)i * Hsz + h]);

#pragma unroll
    for (int t0 = 0; t0 < T; t0 += 16) {
        const int cur = (t0 >> 4) & 1;
        const int nxt = cur ^ 1;
        if (t0 + 16 < T) {
#pragma unroll
            for (int i = 0; i < 16; ++i)
                buf[nxt][i] = __ldg(&g_cur[(size_t)(t0 + 16 + i) * Hsz + h]);
        }
#pragma unroll
        for (int i = 0; i < 16; ++i) {
            m = DECAY * m + buf[cur][i];
            if (m > THRESHOLD) { s += 1.0f; m = 0.0f; }
        }
    }
    g_agg[h] = s * (1.0f / (float)T);
}

// ---------------------------------------------------------------------------
// 4) Output GEMV (out pre-initialized with bias by scan_kernel)
//    512 blocks x 128 threads, 64 h per block, fully unrolled, 2 accumulators.
// ---------------------------------------------------------------------------
#define OUT_OB 128
#define OUT_HB 64

__global__ __launch_bounds__(OUT_OB) void out_gemv_kernel(
    const float* __restrict__ W_out, float* __restrict__ out)
{
    __shared__ float s_agg[OUT_HB];
    const int obase = blockIdx.x * OUT_OB;
    const int hbase = blockIdx.y * OUT_HB;
    const int tid   = threadIdx.x;

    if (tid < OUT_HB) s_agg[tid] = g_agg[hbase + tid];
    __syncthreads();

    const int o = obase + tid;
    const float* __restrict__ Wp = &W_out[(size_t)hbase * Osz + o];
    float acc0 = 0.f, acc1 = 0.f;
#pragma unroll
    for (int hh = 0; hh < OUT_HB; hh += 2) {
        acc0 += s_agg[hh]     * Wp[(size_t)hh * Osz];
        acc1 += s_agg[hh + 1] * Wp[(size_t)(hh + 1) * Osz];
    }
    atomicAdd(&out[o], acc0 + acc1);
}

// ---------------------------------------------------------------------------
extern "C" void kernel_launch(void* const* d_in, const int* in_sizes, int n_in,
                              void* d_out, int out_size) {
    const float* x     = (const float*)d_in[0];  // [B,T,I]
    const float* W_in  = (const float*)d_in[1];  // [I,H]
    const float* b_in  = (const float*)d_in[2];  // [H]
    const float* W_out = (const float*)d_in[3];  // [H,O]
    const float* b_out = (const float*)d_in[4];  // [O]
    const float* m0    = (const float*)d_in[5];  // [H]
    float* out = (float*)d_out;                  // [O]

    // 1) merged reduce + transpose/convert
    prep_kernel<<<RED_BLOCKS + (Hsz / 32) * (Isz / 32), 256>>>(x, W_in);

    // 2) HMMA tensor-core GEMM: grid (4096/128, 256/64) = (32, 4) = 128 CTAs
    cudaFuncSetAttribute(gemm_hmma,
                         cudaFuncAttributeMaxDynamicSharedMemorySize,
                         GEMM_SMEM);
    dim3 gg(Hsz / 128, T / 64);
    gemm_hmma<<<gg, 256, GEMM_SMEM>>>(b_in);

    // 3) scan (+ output bias init): 128 blocks x 32 threads
    scan_kernel<<<Hsz / 32, 32>>>(m0, out, b_out);

    // 4) output GEMV: grid (8, 64) = 512 blocks
    dim3 g4(Osz / OUT_OB, Hsz / OUT_HB);
    out_gemv_kernel<<<g4, OUT_OB>>>(W_out, out);
}

// round 7
// speedup vs baseline: 2.3157x; 1.0885x over previous
#include <cuda_runtime.h>
#include <cuda_bf16.h>
#include <cstdint>

#define Bsz 64
#define T   256
#define Isz 2048
#define Hsz 4096
#define Osz 1024

#define THRESHOLD 1.0f
#define DECAY     0.9f

// ---------------- scratch (device globals; no allocation allowed) ----------
__device__ __nv_bfloat16 g_Ahi[T * Isz];     // 1 MB
__device__ __nv_bfloat16 g_Alo[T * Isz];     // 1 MB
__device__ __nv_bfloat16 g_Bhi[Hsz * Isz];   // 16 MB  [N=4096][K=2048] K-major
__device__ __nv_bfloat16 g_Blo[Hsz * Isz];   // 16 MB
__device__ float g_cur[T * Hsz];             // 4 MB
__device__ float g_agg[Hsz];

// ---------------- PTX helpers ----------------------------------------------
__device__ __forceinline__ uint32_t smem_u32(const void* p) {
    uint32_t a;
    asm("{ .reg .u64 t; cvta.to.shared.u64 t, %1; cvt.u32.u64 %0, t; }"
        : "=r"(a) : "l"(p));
    return a;
}
__device__ __forceinline__ void cp16(uint32_t dst, const void* src) {
    asm volatile("cp.async.cg.shared.global [%0], [%1], 16;" :: "r"(dst), "l"(src));
}
__device__ __forceinline__ void cp_commit() {
    asm volatile("cp.async.commit_group;" ::: "memory");
}
template <int N> __device__ __forceinline__ void cp_wait() {
    asm volatile("cp.async.wait_group %0;" :: "n"(N) : "memory");
}
#define LDSM_X4(r0, r1, r2, r3, addr) \
    asm volatile("ldmatrix.sync.aligned.m8n8.x4.shared.b16 {%0,%1,%2,%3}, [%4];" \
                 : "=r"(r0), "=r"(r1), "=r"(r2), "=r"(r3) : "r"(addr))
#define MMA_BF16(d, a, b0, b1) \
    asm volatile("mma.sync.aligned.m16n8k16.row.col.f32.bf16.bf16.f32 " \
                 "{%0,%1,%2,%3}, {%4,%5,%6,%7}, {%8,%9}, {%0,%1,%2,%3};" \
                 : "+f"((d)[0]), "+f"((d)[1]), "+f"((d)[2]), "+f"((d)[3]) \
                 : "r"((a)[0]), "r"((a)[1]), "r"((a)[2]), "r"((a)[3]), \
                   "r"(b0), "r"(b1))

// ---------------------------------------------------------------------------
// 1) Merged prep: blocks [0,512) batch-reduce x -> A hi/lo;
//    blocks [512, 512+8192) transpose+convert W_in -> B hi/lo.
// ---------------------------------------------------------------------------
#define RED_BLOCKS 512
__global__ __launch_bounds__(256) void prep_kernel(const float* __restrict__ x,
                                                   const float* __restrict__ W) {
    if (blockIdx.x < RED_BLOCKS) {
        const int idx = blockIdx.x * 256 + threadIdx.x;  // over T*I/4
        const int n4  = (T * Isz) / 4;
        const float4* __restrict__ x4 = reinterpret_cast<const float4*>(x);
        float a[4] = {0.f, 0.f, 0.f, 0.f};
#pragma unroll 8
        for (int b = 0; b < Bsz; ++b) {
            float4 v = x4[(size_t)b * n4 + idx];
            a[0] += v.x; a[1] += v.y; a[2] += v.z; a[3] += v.w;
        }
        const float s = 1.0f / (float)Bsz;
        const int base = idx * 4;
#pragma unroll
        for (int i = 0; i < 4; ++i) {
            float v = a[i] * s;
            __nv_bfloat16 hi = __float2bfloat16(v);
            float rem = v - __bfloat162float(hi);
            g_Ahi[base + i] = hi;
            g_Alo[base + i] = __float2bfloat16(rem);
        }
    } else {
        __shared__ float s[32][33];
        const int bid = blockIdx.x - RED_BLOCKS;
        const int h0 = (bid & 127) * 32;   // n tile
        const int i0 = (bid >> 7) * 32;    // k tile
        const int tx = threadIdx.x & 31;
        const int ty = threadIdx.x >> 5;   // 0..7
#pragma unroll
        for (int j = 0; j < 4; ++j) {
            int r = ty + j * 8;
            s[r][tx] = W[(size_t)(i0 + r) * Hsz + h0 + tx];
        }
        __syncthreads();
#pragma unroll
        for (int j = 0; j < 4; ++j) {
            int r = ty + j * 8;          // n offset
            float v = s[tx][r];          // = W[i0+tx][h0+r]
            __nv_bfloat16 hi = __float2bfloat16(v);
            float rem = v - __bfloat162float(hi);
            size_t o = (size_t)(h0 + r) * Isz + i0 + tx;
            g_Bhi[o] = hi;
            g_Blo[o] = __float2bfloat16(rem);
        }
    }
}

// ---------------------------------------------------------------------------
// 2) HMMA bf16 GEMM, fused 3-product hi/lo compensation per k-chunk:
//    acc += Ahi*Bhi + Alo*Bhi + Ahi*Blo   (per BK=64 chunk, tiles loaded once)
//    CTA 64(M)x128(N), 8 warps of 32x32, 3-stage cp.async pipeline.
// ---------------------------------------------------------------------------
#define LDA_B 144                        // 64 bf16 (128B) + 16B pad row stride
#define A_TILE_B (64 * LDA_B)            // 9216
#define B_TILE_B (128 * LDA_B)           // 18432
#define STAGE_B  (2 * A_TILE_B + 2 * B_TILE_B)  // 55296
#define NSTAGE 3
#define GEMM_SMEM (NSTAGE * STAGE_B)     // 165888
#define NCHUNK 32                        // 2048 / 64

__global__ __launch_bounds__(256, 1) void gemm_hmma(const float* __restrict__ b_in) {
    extern __shared__ char smem[];
    const uint32_t sb = smem_u32(smem);
    const int tid  = threadIdx.x;
    const int lane = tid & 31;
    const int wid  = tid >> 5;
    const int m0 = blockIdx.y * 64;
    const int n0 = blockIdx.x * 128;

    const int wm_off = (wid & 1) * 32;   // warp m offset (0/32)
    const int wn_off = (wid >> 1) * 32;  // warp n offset (0/32/64/96)

    float acc[2][4][4];
#pragma unroll
    for (int i = 0; i < 2; ++i)
#pragma unroll
        for (int j = 0; j < 4; ++j)
#pragma unroll
            for (int k = 0; k < 4; ++k) acc[i][j][k] = 0.f;

    auto stage_base = [&](int c) -> uint32_t {
        return sb + (uint32_t)(c % NSTAGE) * STAGE_B;
    };

    // stage layout: [Ahi 9216][Alo 9216][Bhi 18432][Blo 18432]
    auto load_chunk = [&](int c) {
        const int k0 = c << 6;           // k offset (64 per chunk)
        const uint32_t base = stage_base(c);
        // A tiles: 64 rows x 8 cp16 each
#pragma unroll
        for (int i = 0; i < 2; ++i) {
            const int idx = i * 256 + tid;
            const int row = idx >> 3, cc = idx & 7;
            const size_t go = (size_t)(m0 + row) * Isz + k0 + cc * 8;
            const uint32_t so = row * LDA_B + cc * 16;
            cp16(base + so, &g_Ahi[go]);
            cp16(base + A_TILE_B + so, &g_Alo[go]);
        }
        // B tiles: 128 rows x 8 cp16 each
#pragma unroll
        for (int i = 0; i < 4; ++i) {
            const int idx = i * 256 + tid;
            const int row = idx >> 3, cc = idx & 7;
            const size_t go = (size_t)(n0 + row) * Isz + k0 + cc * 8;
            const uint32_t so = row * LDA_B + cc * 16;
            cp16(base + 2 * A_TILE_B + so, &g_Bhi[go]);
            cp16(base + 2 * A_TILE_B + B_TILE_B + so, &g_Blo[go]);
        }
        cp_commit();
    };

    // prologue: 2 chunks in flight
    load_chunk(0); load_chunk(1);

    for (int j = 0; j < NCHUNK; ++j) {
        if (j + 2 < NCHUNK) { load_chunk(j + 2); cp_wait<2>(); }
        else if (j == NCHUNK - 2) cp_wait<1>();
        else                      cp_wait<0>();
        __syncthreads();

        const uint32_t base  = stage_base(j);
        const uint32_t ahi_b = base;
        const uint32_t alo_b = base + A_TILE_B;
        const uint32_t bhi_b = base + 2 * A_TILE_B;
        const uint32_t blo_b = bhi_b + B_TILE_B;
#pragma unroll
        for (int k16 = 0; k16 < 4; ++k16) {
            const uint32_t kbyte = (uint32_t)(k16 * 16 + ((lane >> 4) << 3)) * 2;
            const uint32_t arow = (wm_off + (lane & 15)) * LDA_B + kbyte;
            const uint32_t brow = (wn_off + (lane & 15)) * LDA_B + kbyte;
            uint32_t ahi[2][4], alo[2][4], bhi[2][4], blo[2][4];
#pragma unroll
            for (int mt = 0; mt < 2; ++mt) {
                LDSM_X4(ahi[mt][0], ahi[mt][1], ahi[mt][2], ahi[mt][3],
                        ahi_b + arow + mt * 16 * LDA_B);
                LDSM_X4(alo[mt][0], alo[mt][1], alo[mt][2], alo[mt][3],
                        alo_b + arow + mt * 16 * LDA_B);
            }
#pragma unroll
            for (int nt2 = 0; nt2 < 2; ++nt2) {
                LDSM_X4(bhi[nt2][0], bhi[nt2][1], bhi[nt2][2], bhi[nt2][3],
                        bhi_b + brow + nt2 * 16 * LDA_B);
                LDSM_X4(blo[nt2][0], blo[nt2][1], blo[nt2][2], blo[nt2][3],
                        blo_b + brow + nt2 * 16 * LDA_B);
            }
#pragma unroll
            for (int mt = 0; mt < 2; ++mt)
#pragma unroll
                for (int nt = 0; nt < 4; ++nt) {
                    const int g = nt >> 1, w = nt & 1;
                    MMA_BF16(acc[mt][nt], ahi[mt], bhi[g][w], bhi[g][2 + w]);
                    MMA_BF16(acc[mt][nt], alo[mt], bhi[g][w], bhi[g][2 + w]);
                    MMA_BF16(acc[mt][nt], ahi[mt], blo[g][w], blo[g][2 + w]);
                }
        }
        __syncthreads();
    }

    // epilogue: write g_cur with bias
#pragma unroll
    for (int mt = 0; mt < 2; ++mt) {
#pragma unroll
        for (int nt = 0; nt < 4; ++nt) {
            const int col = n0 + wn_off + nt * 8 + (lane & 3) * 2;
            const float2 bia = *reinterpret_cast<const float2*>(&b_in[col]);
            const int r0 = m0 + wm_off + mt * 16 + (lane >> 2);
            float2 v0, v1;
            v0.x = acc[mt][nt][0] + bia.x;
            v0.y = acc[mt][nt][1] + bia.y;
            v1.x = acc[mt][nt][2] + bia.x;
            v1.y = acc[mt][nt][3] + bia.y;
            *reinterpret_cast<float2*>(&g_cur[(size_t)r0 * Hsz + col]) = v0;
            *reinterpret_cast<float2*>(&g_cur[(size_t)(r0 + 8) * Hsz + col]) = v1;
        }
    }
}

// ---------------------------------------------------------------------------
// 3) LIF scan: 128 blocks x 32 threads, software-pipelined 16-deep prefetch.
//    Also initializes out[] = b_out[] (blocks 0..31) ahead of the GEMV.
// ---------------------------------------------------------------------------
__global__ __launch_bounds__(32) void scan_kernel(const float* __restrict__ m0,
                                                  float* __restrict__ out,
                                                  const float* __restrict__ b_out) {
    const int h = blockIdx.x * 32 + threadIdx.x;
    if (blockIdx.x < Osz / 32) out[h] = b_out[h];

    float m = m0[h];
    float s = 0.f;
    float buf[2][16];
#pragma unroll
    for (int i = 0; i < 16; ++i)
        buf[0][i] = __ldg(&g_cur[(size_t)i * Hsz + h]);

#pragma unroll
    for (int t0 = 0; t0 < T; t0 += 16) {
        const int cur = (t0 >> 4) & 1;
        const int nxt = cur ^ 1;
        if (t0 + 16 < T) {
#pragma unroll
            for (int i = 0; i < 16; ++i)
                buf[nxt][i] = __ldg(&g_cur[(size_t)(t0 + 16 + i) * Hsz + h]);
        }
#pragma unroll
        for (int i = 0; i < 16; ++i) {
            m = DECAY * m + buf[cur][i];
            if (m > THRESHOLD) { s += 1.0f; m = 0.0f; }
        }
    }
    g_agg[h] = s * (1.0f / (float)T);
}

// ---------------------------------------------------------------------------
// 4) Output GEMV (out pre-initialized with bias by scan_kernel)
//    512 blocks x 128 threads, 64 h per block, fully unrolled, 2 accumulators.
// ---------------------------------------------------------------------------
#define OUT_OB 128
#define OUT_HB 64

__global__ __launch_bounds__(OUT_OB) void out_gemv_kernel(
    const float* __restrict__ W_out, float* __restrict__ out)
{
    __shared__ float s_agg[OUT_HB];
    const int obase = blockIdx.x * OUT_OB;
    const int hbase = blockIdx.y * OUT_HB;
    const int tid   = threadIdx.x;

    if (tid < OUT_HB) s_agg[tid] = g_agg[hbase + tid];
    __syncthreads();

    const int o = obase + tid;
    const float* __restrict__ Wp = &W_out[(size_t)hbase * Osz + o];
    float acc0 = 0.f, acc1 = 0.f;
#pragma unroll
    for (int hh = 0; hh < OUT_HB; hh += 2) {
        acc0 += s_agg[hh]     * Wp[(size_t)hh * Osz];
        acc1 += s_agg[hh + 1] * Wp[(size_t)(hh + 1) * Osz];
    }
    atomicAdd(&out[o], acc0 + acc1);
}

// ---------------------------------------------------------------------------
extern "C" void kernel_launch(void* const* d_in, const int* in_sizes, int n_in,
                              void* d_out, int out_size) {
    const float* x     = (const float*)d_in[0];  // [B,T,I]
    const float* W_in  = (const float*)d_in[1];  // [I,H]
    const float* b_in  = (const float*)d_in[2];  // [H]
    const float* W_out = (const float*)d_in[3];  // [H,O]
    const float* b_out = (const float*)d_in[4];  // [O]
    const float* m0    = (const float*)d_in[5];  // [H]
    float* out = (float*)d_out;                  // [O]

    // 1) merged reduce + transpose/convert
    prep_kernel<<<RED_BLOCKS + (Hsz / 32) * (Isz / 32), 256>>>(x, W_in);

    // 2) HMMA tensor-core GEMM: grid (4096/128, 256/64) = (32, 4) = 128 CTAs
    cudaFuncSetAttribute(gemm_hmma,
                         cudaFuncAttributeMaxDynamicSharedMemorySize,
                         GEMM_SMEM);
    dim3 gg(Hsz / 128, T / 64);
    gemm_hmma<<<gg, 256, GEMM_SMEM>>>(b_in);

    // 3) scan (+ output bias init): 128 blocks x 32 threads
    scan_kernel<<<Hsz / 32, 32>>>(m0, out, b_out);

    // 4) output GEMV: grid (8, 64) = 512 blocks
    dim3 g4(Osz / OUT_OB, Hsz / OUT_HB);
    out_gemv_kernel<<<g4, OUT_OB>>>(W_out, out);
}